// round 7
// baseline (speedup 1.0000x reference)
#include <cuda_runtime.h>
#include <cuda_bf16.h>
#include <cstdint>

// ---------------------------------------------------------------------------
// Problem constants
// ---------------------------------------------------------------------------
#define DIM   512
#define NNODE 65536
#define MMUT  32768

// ---------------------------------------------------------------------------
// Smem tile geometry: CTA tile 128x128, K-stage 32, rows padded to 40 bf16
// ---------------------------------------------------------------------------
#define RS      40                  // row stride in bf16 (80 bytes)
#define MAT_ELE (128 * RS)          // one 128x32(+pad) matrix = 5120 bf16
#define BUF_ELE (4 * MAT_ELE)       // A_hi, A_lo, B_hi, B_lo
#define SMEM_BYTES (2 * BUF_ELE * 2)  // double buffered = 81920 B

#define DI __device__ __forceinline__

// ---------------------------------------------------------------------------
// Device scratch (__device__ globals only — no allocations)
// ---------------------------------------------------------------------------
__device__ __nv_bfloat16 g_wo_hi[DIM * DIM];
__device__ __nv_bfloat16 g_wo_lo[DIM * DIM];
__device__ __nv_bfloat16 g_wc_hi[DIM * DIM];
__device__ __nv_bfloat16 g_wc_lo[DIM * DIM];
__device__ __nv_bfloat16 g_lin_hi[DIM * 2 * DIM];
__device__ __nv_bfloat16 g_lin_lo[DIM * 2 * DIM];
// gathered + tanh'd + split GEMM2 A matrix: [MMUT, 1024] bf16 hi/lo
__device__ __nv_bfloat16 g_gh[(size_t)MMUT * 2 * DIM];
__device__ __nv_bfloat16 g_gl[(size_t)MMUT * 2 * DIM];

// ---------------------------------------------------------------------------
// Helpers
// ---------------------------------------------------------------------------
DI uint32_t smem_u32(const void* p) {
    uint32_t a;
    asm("{ .reg .u64 t; cvta.to.shared.u64 t, %1; cvt.u32.u64 %0, t; }"
        : "=r"(a) : "l"(p));
    return a;
}

DI void split_bf16(float v, __nv_bfloat16& h, __nv_bfloat16& l) {
    h = __float2bfloat16(v);
    l = __float2bfloat16(v - __bfloat162float(h));
}

DI void ldsm_x4(uint32_t* r, uint32_t addr) {
    asm volatile("ldmatrix.sync.aligned.m8n8.x4.shared.b16 {%0,%1,%2,%3}, [%4];"
                 : "=r"(r[0]), "=r"(r[1]), "=r"(r[2]), "=r"(r[3]) : "r"(addr));
}

DI void mma_bf16(float* c, const uint32_t* a, uint32_t b0, uint32_t b1) {
    asm volatile(
        "mma.sync.aligned.m16n8k16.row.col.f32.bf16.bf16.f32 "
        "{%0,%1,%2,%3}, {%4,%5,%6,%7}, {%8,%9}, {%0,%1,%2,%3};"
        : "+f"(c[0]), "+f"(c[1]), "+f"(c[2]), "+f"(c[3])
        : "r"(a[0]), "r"(a[1]), "r"(a[2]), "r"(a[3]), "r"(b0), "r"(b1));
}

// One K-stage (32) of the split-bf16 warp-tile MMA: 2 k16 steps, warp 32x64.
DI void compute_stage(const __nv_bfloat16* sbuf, int lane, int wm, int wn,
                      float acc[2][8][4]) {
    uint32_t base = smem_u32(sbuf);
    const uint32_t sAhi = base;
    const uint32_t sAlo = base + MAT_ELE * 2;
    const uint32_t sBhi = base + MAT_ELE * 4;
    const uint32_t sBlo = base + MAT_ELE * 6;
    const int lrow = lane & 15;
    const int lkh  = lane >> 4;
#pragma unroll
    for (int ks = 0; ks < 2; ++ks) {
        const uint32_t kbyte = (uint32_t)(ks * 16 + 8 * lkh) * 2;
        uint32_t ah[2][4], al[2][4];
#pragma unroll
        for (int mt = 0; mt < 2; ++mt) {
            uint32_t off = (uint32_t)((wm * 32 + mt * 16 + lrow) * (RS * 2)) + kbyte;
            ldsm_x4(ah[mt], sAhi + off);
            ldsm_x4(al[mt], sAlo + off);
        }
        uint32_t bh[4][4], bl[4][4];
#pragma unroll
        for (int np = 0; np < 4; ++np) {
            uint32_t off = (uint32_t)((wn * 64 + np * 16 + lrow) * (RS * 2)) + kbyte;
            ldsm_x4(bh[np], sBhi + off);
            ldsm_x4(bl[np], sBlo + off);
        }
#pragma unroll
        for (int mt = 0; mt < 2; ++mt)
#pragma unroll
            for (int nt = 0; nt < 8; ++nt) {
                const int np = nt >> 1, w = nt & 1;
                mma_bf16(acc[mt][nt], ah[mt], bh[np][w], bh[np][w + 2]); // hi*hi
                mma_bf16(acc[mt][nt], al[mt], bh[np][w], bh[np][w + 2]); // lo*hi
                mma_bf16(acc[mt][nt], ah[mt], bl[np][w], bl[np][w + 2]); // hi*lo
            }
    }
}

// ---------------------------------------------------------------------------
// prep: split weights to bf16 hi/lo (+ transpose W_o, W_c to [n][k])
// ---------------------------------------------------------------------------
__global__ void prep_kernel(const float* __restrict__ wo, const float* __restrict__ wc,
                            const float* __restrict__ lw) {
    int i = blockIdx.x * 256 + threadIdx.x;   // 0 .. 512*1024-1
    int n = i >> 10;
    int k = i & 1023;

    __nv_bfloat16 h, l;
    split_bf16(lw[i], h, l);                  // lin_w is [512][1024] = [n][k]
    g_lin_hi[i] = h;
    g_lin_lo[i] = l;

    if (k < 512) {
        int src = k * 512 + n;                // B[n][k] = W[k][n]
        int dst = n * 512 + k;
        split_bf16(wo[src], h, l);
        g_wo_hi[dst] = h; g_wo_lo[dst] = l;
        split_bf16(wc[src], h, l);
        g_wc_hi[dst] = h; g_wc_lo[dst] = l;
    }
}

// ---------------------------------------------------------------------------
// GEMM1: trans_hp = h_p @ W_o ; trans_hk = h_k @ W_c   (fp32 A split on the fly)
// grid (4 n-tiles, 512 m-tiles, 2), block 256
// ---------------------------------------------------------------------------
__global__ __launch_bounds__(256) void gemm1_kernel(
    const float* __restrict__ hp, const float* __restrict__ hk,
    float* __restrict__ out) {
    extern __shared__ __align__(16) __nv_bfloat16 sm[];
    const int tid = threadIdx.x, lane = tid & 31, wid = tid >> 5;
    const int wm = wid & 3, wn = wid >> 2;
    const int n0 = blockIdx.x * 128, m0 = blockIdx.y * 128, z = blockIdx.z;

    const float* A = z ? hk : hp;
    const __nv_bfloat16* Bh = z ? g_wc_hi : g_wo_hi;
    const __nv_bfloat16* Bl = z ? g_wc_lo : g_wo_lo;
    float* dst = out + (size_t)z * NNODE * DIM;

    const int arow = tid >> 4, acol = (tid & 15) * 2;   // A: 16 rows/iter, float2
    const int brow = tid >> 2, bq = tid & 3;            // B: 64 rows/iter, uint4

    float acc[2][8][4];
#pragma unroll
    for (int i = 0; i < 2; ++i)
#pragma unroll
        for (int j = 0; j < 8; ++j)
#pragma unroll
            for (int k = 0; k < 4; ++k) acc[i][j][k] = 0.f;

    float2 ar[8];
    uint4  bhr[2], blr[2];

    auto loadA = [&](int k0) {
#pragma unroll
        for (int it = 0; it < 8; ++it)
            ar[it] = *reinterpret_cast<const float2*>(
                A + (size_t)(m0 + it * 16 + arow) * DIM + k0 + acol);
    };
    auto loadB = [&](int k0) {
#pragma unroll
        for (int it = 0; it < 2; ++it) {
            size_t o = (size_t)(n0 + it * 64 + brow) * DIM + k0 + bq * 8;
            bhr[it] = *reinterpret_cast<const uint4*>(Bh + o);
            blr[it] = *reinterpret_cast<const uint4*>(Bl + o);
        }
    };
    auto store = [&](int buf) {
        __nv_bfloat16* sA_hi = sm + buf * BUF_ELE;
        __nv_bfloat16* sA_lo = sA_hi + MAT_ELE;
        __nv_bfloat16* sB_hi = sA_hi + 2 * MAT_ELE;
        __nv_bfloat16* sB_lo = sA_hi + 3 * MAT_ELE;
#pragma unroll
        for (int it = 0; it < 8; ++it) {
            __nv_bfloat16 h0, l0, h1, l1;
            split_bf16(ar[it].x, h0, l0);
            split_bf16(ar[it].y, h1, l1);
            int r = it * 16 + arow;
            __nv_bfloat162 ph; ph.x = h0; ph.y = h1;
            __nv_bfloat162 pl; pl.x = l0; pl.y = l1;
            *reinterpret_cast<__nv_bfloat162*>(sA_hi + r * RS + acol) = ph;
            *reinterpret_cast<__nv_bfloat162*>(sA_lo + r * RS + acol) = pl;
        }
#pragma unroll
        for (int it = 0; it < 2; ++it) {
            int r = it * 64 + brow;
            *reinterpret_cast<uint4*>(sB_hi + r * RS + bq * 8) = bhr[it];
            *reinterpret_cast<uint4*>(sB_lo + r * RS + bq * 8) = blr[it];
        }
    };

    loadA(0); loadB(0);
    store(0);
    __syncthreads();

#pragma unroll 1
    for (int s = 0; s < DIM / 32; ++s) {
        if (s + 1 < DIM / 32) { loadA((s + 1) * 32); loadB((s + 1) * 32); }
        compute_stage(sm + (s & 1) * BUF_ELE, lane, wm, wn, acc);
        if (s + 1 < DIM / 32) store((s + 1) & 1);
        __syncthreads();
    }

#pragma unroll
    for (int mt = 0; mt < 2; ++mt) {
        int grow = m0 + wm * 32 + mt * 16 + (lane >> 2);
#pragma unroll
        for (int nt = 0; nt < 8; ++nt) {
            int gcol = n0 + wn * 64 + nt * 8 + (lane & 3) * 2;
            float2 v0; v0.x = acc[mt][nt][0]; v0.y = acc[mt][nt][1];
            float2 v1; v1.x = acc[mt][nt][2]; v1.y = acc[mt][nt][3];
            *reinterpret_cast<float2*>(dst + (size_t)grow * DIM + gcol) = v0;
            *reinterpret_cast<float2*>(dst + (size_t)(grow + 8) * DIM + gcol) = v1;
        }
    }
}

// ---------------------------------------------------------------------------
// gather + tanh + bf16 split:  g_g[m][0:512]  = split(tanh(trans_hp[idxp[m]]))
//                              g_g[m][512:1024]= split(tanh(trans_hk[idxk[m]]))
// ---------------------------------------------------------------------------
__global__ void gather_tanh_kernel(const float* __restrict__ out,
                                   const int* __restrict__ idxp,
                                   const int* __restrict__ idxk) {
    const int m = blockIdx.x;
    const int t = threadIdx.x;                 // 256 threads, 2 cols each half
    const float* outp = out;
    const float* outk = out + (size_t)NNODE * DIM;
    const int rp = idxp[m], rk = idxk[m];

    float2 v = *reinterpret_cast<const float2*>(outp + (size_t)rp * DIM + 2 * t);
    float2 w = *reinterpret_cast<const float2*>(outk + (size_t)rk * DIM + 2 * t);

    __nv_bfloat16 h0, l0, h1, l1;
    size_t base = (size_t)m * (2 * DIM);

    split_bf16(tanhf(v.x), h0, l0);
    split_bf16(tanhf(v.y), h1, l1);
    __nv_bfloat162 ph; ph.x = h0; ph.y = h1;
    __nv_bfloat162 pl; pl.x = l0; pl.y = l1;
    *reinterpret_cast<__nv_bfloat162*>(g_gh + base + 2 * t) = ph;
    *reinterpret_cast<__nv_bfloat162*>(g_gl + base + 2 * t) = pl;

    split_bf16(tanhf(w.x), h0, l0);
    split_bf16(tanhf(w.y), h1, l1);
    ph.x = h0; ph.y = h1;
    pl.x = l0; pl.y = l1;
    *reinterpret_cast<__nv_bfloat162*>(g_gh + base + DIM + 2 * t) = ph;
    *reinterpret_cast<__nv_bfloat162*>(g_gl + base + DIM + 2 * t) = pl;
}

// ---------------------------------------------------------------------------
// GEMM2: out-rows = leaky_relu(g @ lin_w^T + lin_b) + bias, scattered into
//        BOTH halves of d_out directly (g_mid eliminated).
// grid (4 n-tiles, 256 m-tiles), block 256
// ---------------------------------------------------------------------------
__global__ __launch_bounds__(256) void gemm2_kernel(
    const int* __restrict__ idxp, const int* __restrict__ idxk,
    const float* __restrict__ lin_b, const float* __restrict__ bias,
    float* __restrict__ out) {
    extern __shared__ __align__(16) __nv_bfloat16 sm[];
    const int tid = threadIdx.x, lane = tid & 31, wid = tid >> 5;
    const int wm = wid & 3, wn = wid >> 2;
    const int n0 = blockIdx.x * 128, m0 = blockIdx.y * 128;

    float* outp = out;
    float* outk = out + (size_t)NNODE * DIM;

    const int brow = tid >> 2, bq = tid & 3;   // both operands pre-split bf16

    float acc[2][8][4];
#pragma unroll
    for (int i = 0; i < 2; ++i)
#pragma unroll
        for (int j = 0; j < 8; ++j)
#pragma unroll
            for (int k = 0; k < 4; ++k) acc[i][j][k] = 0.f;

    uint4 ahr[2], alr[2], bhr[2], blr[2];

    auto loadA = [&](int k0) {
#pragma unroll
        for (int it = 0; it < 2; ++it) {
            size_t o = (size_t)(m0 + it * 64 + brow) * (2 * DIM) + k0 + bq * 8;
            ahr[it] = *reinterpret_cast<const uint4*>(g_gh + o);
            alr[it] = *reinterpret_cast<const uint4*>(g_gl + o);
        }
    };
    auto loadB = [&](int k0) {
#pragma unroll
        for (int it = 0; it < 2; ++it) {
            size_t o = (size_t)(n0 + it * 64 + brow) * (2 * DIM) + k0 + bq * 8;
            bhr[it] = *reinterpret_cast<const uint4*>(g_lin_hi + o);
            blr[it] = *reinterpret_cast<const uint4*>(g_lin_lo + o);
        }
    };
    auto store = [&](int buf) {
        __nv_bfloat16* sA_hi = sm + buf * BUF_ELE;
        __nv_bfloat16* sA_lo = sA_hi + MAT_ELE;
        __nv_bfloat16* sB_hi = sA_hi + 2 * MAT_ELE;
        __nv_bfloat16* sB_lo = sA_hi + 3 * MAT_ELE;
#pragma unroll
        for (int it = 0; it < 2; ++it) {
            int r = it * 64 + brow;
            *reinterpret_cast<uint4*>(sA_hi + r * RS + bq * 8) = ahr[it];
            *reinterpret_cast<uint4*>(sA_lo + r * RS + bq * 8) = alr[it];
            *reinterpret_cast<uint4*>(sB_hi + r * RS + bq * 8) = bhr[it];
            *reinterpret_cast<uint4*>(sB_lo + r * RS + bq * 8) = blr[it];
        }
    };

    loadA(0); loadB(0);
    store(0);
    __syncthreads();

    const int S = (2 * DIM) / 32;   // 32 stages
#pragma unroll 1
    for (int s = 0; s < S; ++s) {
        if (s + 1 < S) { loadA((s + 1) * 32); loadB((s + 1) * 32); }
        compute_stage(sm + (s & 1) * BUF_ELE, lane, wm, wn, acc);
        if (s + 1 < S) store((s + 1) & 1);
        __syncthreads();
    }

#pragma unroll
    for (int mt = 0; mt < 2; ++mt) {
        int grow = m0 + wm * 32 + mt * 16 + (lane >> 2);
        int p0 = idxp[grow], p1 = idxp[grow + 8];
        int q0 = idxk[grow], q1 = idxk[grow + 8];
#pragma unroll
        for (int nt = 0; nt < 8; ++nt) {
            int gcol = n0 + wn * 64 + nt * 8 + (lane & 3) * 2;
            float2 lb = *reinterpret_cast<const float2*>(lin_b + gcol);
            float2 bs = *reinterpret_cast<const float2*>(bias + gcol);
            float x0 = acc[mt][nt][0] + lb.x;
            float x1 = acc[mt][nt][1] + lb.y;
            float x2 = acc[mt][nt][2] + lb.x;
            float x3 = acc[mt][nt][3] + lb.y;
            x0 = (x0 >= 0.f ? x0 : 0.01f * x0) + bs.x;
            x1 = (x1 >= 0.f ? x1 : 0.01f * x1) + bs.y;
            x2 = (x2 >= 0.f ? x2 : 0.01f * x2) + bs.x;
            x3 = (x3 >= 0.f ? x3 : 0.01f * x3) + bs.y;
            float2 v0; v0.x = x0; v0.y = x1;
            float2 v1; v1.x = x2; v1.y = x3;
            *reinterpret_cast<float2*>(outp + (size_t)p0 * DIM + gcol) = v0;
            *reinterpret_cast<float2*>(outp + (size_t)p1 * DIM + gcol) = v1;
            *reinterpret_cast<float2*>(outk + (size_t)q0 * DIM + gcol) = v0;
            *reinterpret_cast<float2*>(outk + (size_t)q1 * DIM + gcol) = v1;
        }
    }
}

// ---------------------------------------------------------------------------
// Launch
// ---------------------------------------------------------------------------
extern "C" void kernel_launch(void* const* d_in, const int* in_sizes, int n_in,
                              void* d_out, int out_size) {
    const float* h_p  = (const float*)d_in[0];
    const float* h_k  = (const float*)d_in[1];
    const int*   idxp = (const int*)d_in[2];
    const int*   idxk = (const int*)d_in[3];
    // d_in[4] = last_x (unused by the reference computation)
    const float* wo   = (const float*)d_in[5];
    const float* wc   = (const float*)d_in[6];
    const float* lw   = (const float*)d_in[7];
    const float* lb   = (const float*)d_in[8];
    const float* bias = (const float*)d_in[9];
    float* out = (float*)d_out;

    cudaFuncSetAttribute(gemm1_kernel, cudaFuncAttributeMaxDynamicSharedMemorySize, SMEM_BYTES);
    cudaFuncSetAttribute(gemm2_kernel, cudaFuncAttributeMaxDynamicSharedMemorySize, SMEM_BYTES);

    prep_kernel<<<(512 * 1024) / 256, 256>>>(wo, wc, lw);

    gemm1_kernel<<<dim3(DIM / 128, NNODE / 128, 2), 256, SMEM_BYTES>>>(h_p, h_k, out);

    gather_tanh_kernel<<<MMUT, 256>>>(out, idxp, idxk);

    gemm2_kernel<<<dim3(DIM / 128, MMUT / 128), 256, SMEM_BYTES>>>(idxp, idxk, lb, bias, out);
}

// round 8
// speedup vs baseline: 1.0907x; 1.0907x over previous
#include <cuda_runtime.h>
#include <cuda_bf16.h>
#include <cstdint>

// ---------------------------------------------------------------------------
// Problem constants
// ---------------------------------------------------------------------------
#define DIM   512
#define NNODE 65536
#define MMUT  32768

// ---------------------------------------------------------------------------
// Smem tile geometry: CTA tile 128x128, K-stage 32, rows padded to 40 bf16
// ---------------------------------------------------------------------------
#define RS      40                    // row stride in bf16 (80 bytes)
#define MAT_ELE (128 * RS)            // one 128x32(+pad) matrix = 5120 bf16
#define BUF_ELE (4 * MAT_ELE)         // A_hi, A_lo, B_hi, B_lo
#define BUF_BYTES (BUF_ELE * 2)       // 40960
#define SMEM_BYTES (2 * BUF_BYTES)    // double buffered = 81920 B

#define DI __device__ __forceinline__

// ---------------------------------------------------------------------------
// Device scratch (__device__ globals only — no allocations)
// ---------------------------------------------------------------------------
__device__ __nv_bfloat16 g_wo_hi[DIM * DIM];
__device__ __nv_bfloat16 g_wo_lo[DIM * DIM];
__device__ __nv_bfloat16 g_wc_hi[DIM * DIM];
__device__ __nv_bfloat16 g_wc_lo[DIM * DIM];
__device__ __nv_bfloat16 g_lin_hi[DIM * 2 * DIM];
__device__ __nv_bfloat16 g_lin_lo[DIM * 2 * DIM];
// pre-split inputs: h_p, h_k as bf16 hi/lo
__device__ __nv_bfloat16 g_hp_hi[(size_t)NNODE * DIM];
__device__ __nv_bfloat16 g_hp_lo[(size_t)NNODE * DIM];
__device__ __nv_bfloat16 g_hk_hi[(size_t)NNODE * DIM];
__device__ __nv_bfloat16 g_hk_lo[(size_t)NNODE * DIM];
// gathered + tanh'd + split GEMM2 A matrix: [MMUT, 1024] bf16 hi/lo
__device__ __nv_bfloat16 g_gh[(size_t)MMUT * 2 * DIM];
__device__ __nv_bfloat16 g_gl[(size_t)MMUT * 2 * DIM];

// ---------------------------------------------------------------------------
// Helpers
// ---------------------------------------------------------------------------
DI uint32_t smem_u32(const void* p) {
    uint32_t a;
    asm("{ .reg .u64 t; cvta.to.shared.u64 t, %1; cvt.u32.u64 %0, t; }"
        : "=r"(a) : "l"(p));
    return a;
}

DI void split_bf16(float v, __nv_bfloat16& h, __nv_bfloat16& l) {
    h = __float2bfloat16(v);
    l = __float2bfloat16(v - __bfloat162float(h));
}

DI void ldsm_x4(uint32_t* r, uint32_t addr) {
    asm volatile("ldmatrix.sync.aligned.m8n8.x4.shared.b16 {%0,%1,%2,%3}, [%4];"
                 : "=r"(r[0]), "=r"(r[1]), "=r"(r[2]), "=r"(r[3]) : "r"(addr));
}

DI void mma_bf16(float* c, const uint32_t* a, uint32_t b0, uint32_t b1) {
    asm volatile(
        "mma.sync.aligned.m16n8k16.row.col.f32.bf16.bf16.f32 "
        "{%0,%1,%2,%3}, {%4,%5,%6,%7}, {%8,%9}, {%0,%1,%2,%3};"
        : "+f"(c[0]), "+f"(c[1]), "+f"(c[2]), "+f"(c[3])
        : "r"(a[0]), "r"(a[1]), "r"(a[2]), "r"(a[3]), "r"(b0), "r"(b1));
}

DI void cp_async16(uint32_t saddr, const void* gptr) {
    asm volatile("cp.async.cg.shared.global [%0], [%1], 16;"
                 :: "r"(saddr), "l"(gptr));
}
DI void cp_commit() { asm volatile("cp.async.commit_group;" ::: "memory"); }
template <int N> DI void cp_wait() {
    asm volatile("cp.async.wait_group %0;" :: "n"(N) : "memory");
}

// ---------------------------------------------------------------------------
// One K-stage (32) of the split-bf16 warp-tile MMA: 2 k16 steps, warp 32x64.
// (identical math to the validated R6 version)
// ---------------------------------------------------------------------------
DI void compute_stage(uint32_t base, int lane, int wm, int wn,
                      float acc[2][8][4]) {
    const uint32_t sAhi = base;
    const uint32_t sAlo = base + MAT_ELE * 2;
    const uint32_t sBhi = base + MAT_ELE * 4;
    const uint32_t sBlo = base + MAT_ELE * 6;
    const int lrow = lane & 15;
    const int lkh  = lane >> 4;
#pragma unroll
    for (int ks = 0; ks < 2; ++ks) {
        const uint32_t kbyte = (uint32_t)(ks * 16 + 8 * lkh) * 2;
        uint32_t ah[2][4], al[2][4];
#pragma unroll
        for (int mt = 0; mt < 2; ++mt) {
            uint32_t off = (uint32_t)((wm * 32 + mt * 16 + lrow) * (RS * 2)) + kbyte;
            ldsm_x4(ah[mt], sAhi + off);
            ldsm_x4(al[mt], sAlo + off);
        }
#pragma unroll
        for (int np = 0; np < 4; ++np) {
            uint32_t off = (uint32_t)((wn * 64 + np * 16 + lrow) * (RS * 2)) + kbyte;
            uint32_t bh[4], bl[4];
            ldsm_x4(bh, sBhi + off);
            ldsm_x4(bl, sBlo + off);
#pragma unroll
            for (int mt = 0; mt < 2; ++mt)
#pragma unroll
                for (int w = 0; w < 2; ++w) {
                    float* c = acc[mt][np * 2 + w];
                    mma_bf16(c, ah[mt], bh[w], bh[w + 2]);   // hi*hi
                    mma_bf16(c, al[mt], bh[w], bh[w + 2]);   // lo*hi
                    mma_bf16(c, ah[mt], bl[w], bl[w + 2]);   // hi*lo
                }
        }
    }
}

// ---------------------------------------------------------------------------
// cp.async one stage: 4 matrices x 128 rows x 64B, 8 chunks of 16B per thread
// mat = i>>1 (0:A_hi 1:A_lo 2:B_hi 3:B_lo), row = (i&1)*64 + tid/4, q = tid&3
// ---------------------------------------------------------------------------
DI void stage_cp(uint32_t sbase,
                 const __nv_bfloat16* Ah, const __nv_bfloat16* Al,
                 const __nv_bfloat16* Bh, const __nv_bfloat16* Bl,
                 int ldA, int ldB, int m0, int n0, int k0, int tid) {
    const int q = tid & 3;
    const int r = tid >> 2;
#pragma unroll
    for (int i = 0; i < 8; ++i) {
        const int mat = i >> 1;
        const int row = (i & 1) * 64 + r;
        const __nv_bfloat16* p = (mat == 0) ? Ah : (mat == 1) ? Al
                               : (mat == 2) ? Bh : Bl;
        const int ld = (mat < 2) ? ldA : ldB;
        const int r0 = (mat < 2) ? m0 : n0;
        uint32_t sa = sbase + (uint32_t)(mat * (MAT_ELE * 2) + row * (RS * 2) + q * 16);
        cp_async16(sa, p + (size_t)(r0 + row) * ld + k0 + q * 8);
    }
}

// ---------------------------------------------------------------------------
// prep: split weights to bf16 hi/lo (+ transpose W_o, W_c to [n][k])
// ---------------------------------------------------------------------------
__global__ void prep_kernel(const float* __restrict__ wo, const float* __restrict__ wc,
                            const float* __restrict__ lw) {
    int i = blockIdx.x * 256 + threadIdx.x;   // 0 .. 512*1024-1
    int n = i >> 10;
    int k = i & 1023;

    __nv_bfloat16 h, l;
    split_bf16(lw[i], h, l);                  // lin_w is [512][1024] = [n][k]
    g_lin_hi[i] = h;
    g_lin_lo[i] = l;

    if (k < 512) {
        int src = k * 512 + n;                // B[n][k] = W[k][n]
        int dst = n * 512 + k;
        split_bf16(wo[src], h, l);
        g_wo_hi[dst] = h; g_wo_lo[dst] = l;
        split_bf16(wc[src], h, l);
        g_wc_hi[dst] = h; g_wc_lo[dst] = l;
    }
}

// ---------------------------------------------------------------------------
// split inputs: h_p, h_k fp32 -> bf16 hi/lo  (pure bandwidth pass)
// ---------------------------------------------------------------------------
__global__ void split_inputs_kernel(const float* __restrict__ hp,
                                    const float* __restrict__ hk) {
    const size_t idx = (size_t)blockIdx.x * 256 + threadIdx.x;   // float2 index
    const int z = blockIdx.y;
    const float* src = z ? hk : hp;
    __nv_bfloat16* dh = z ? g_hk_hi : g_hp_hi;
    __nv_bfloat16* dl = z ? g_hk_lo : g_hp_lo;

    float2 v = *reinterpret_cast<const float2*>(src + idx * 2);
    __nv_bfloat16 h0, l0, h1, l1;
    split_bf16(v.x, h0, l0);
    split_bf16(v.y, h1, l1);
    __nv_bfloat162 ph; ph.x = h0; ph.y = h1;
    __nv_bfloat162 pl; pl.x = l0; pl.y = l1;
    *reinterpret_cast<__nv_bfloat162*>(dh + idx * 2) = ph;
    *reinterpret_cast<__nv_bfloat162*>(dl + idx * 2) = pl;
}

// ---------------------------------------------------------------------------
// GEMM1: trans_hp = h_p @ W_o ; trans_hk = h_k @ W_c   (all operands pre-split)
// grid (4 n-tiles, 512 m-tiles, 2), block 256, 2 CTAs/SM
// ---------------------------------------------------------------------------
__global__ __launch_bounds__(256, 2) void gemm1_kernel(float* __restrict__ out) {
    extern __shared__ __align__(16) __nv_bfloat16 sm[];
    const int tid = threadIdx.x, lane = tid & 31, wid = tid >> 5;
    const int wm = wid & 3, wn = wid >> 2;
    const int n0 = blockIdx.x * 128, m0 = blockIdx.y * 128, z = blockIdx.z;

    const __nv_bfloat16* Ah = z ? g_hk_hi : g_hp_hi;
    const __nv_bfloat16* Al = z ? g_hk_lo : g_hp_lo;
    const __nv_bfloat16* Bh = z ? g_wc_hi : g_wo_hi;
    const __nv_bfloat16* Bl = z ? g_wc_lo : g_wo_lo;
    float* dst = out + (size_t)z * NNODE * DIM;

    float acc[2][8][4];
#pragma unroll
    for (int i = 0; i < 2; ++i)
#pragma unroll
        for (int j = 0; j < 8; ++j)
#pragma unroll
            for (int k = 0; k < 4; ++k) acc[i][j][k] = 0.f;

    const uint32_t sb = smem_u32(sm);

    stage_cp(sb, Ah, Al, Bh, Bl, DIM, DIM, m0, n0, 0, tid);
    cp_commit();

    const int S = DIM / 32;   // 16 stages
#pragma unroll 1
    for (int s = 0; s < S; ++s) {
        if (s + 1 < S) {
            stage_cp(sb + ((s + 1) & 1) * BUF_BYTES, Ah, Al, Bh, Bl,
                     DIM, DIM, m0, n0, (s + 1) * 32, tid);
            cp_commit();
            cp_wait<1>();
        } else {
            cp_wait<0>();
        }
        __syncthreads();
        compute_stage(sb + (s & 1) * BUF_BYTES, lane, wm, wn, acc);
        __syncthreads();
    }

#pragma unroll
    for (int mt = 0; mt < 2; ++mt) {
        int grow = m0 + wm * 32 + mt * 16 + (lane >> 2);
#pragma unroll
        for (int nt = 0; nt < 8; ++nt) {
            int gcol = n0 + wn * 64 + nt * 8 + (lane & 3) * 2;
            float2 v0; v0.x = acc[mt][nt][0]; v0.y = acc[mt][nt][1];
            float2 v1; v1.x = acc[mt][nt][2]; v1.y = acc[mt][nt][3];
            *reinterpret_cast<float2*>(dst + (size_t)grow * DIM + gcol) = v0;
            *reinterpret_cast<float2*>(dst + (size_t)(grow + 8) * DIM + gcol) = v1;
        }
    }
}

// ---------------------------------------------------------------------------
// gather + tanh + bf16 split
// ---------------------------------------------------------------------------
__global__ void gather_tanh_kernel(const float* __restrict__ out,
                                   const int* __restrict__ idxp,
                                   const int* __restrict__ idxk) {
    const int m = blockIdx.x;
    const int t = threadIdx.x;                 // 256 threads, 2 cols each half
    const float* outp = out;
    const float* outk = out + (size_t)NNODE * DIM;
    const int rp = idxp[m], rk = idxk[m];

    float2 v = *reinterpret_cast<const float2*>(outp + (size_t)rp * DIM + 2 * t);
    float2 w = *reinterpret_cast<const float2*>(outk + (size_t)rk * DIM + 2 * t);

    __nv_bfloat16 h0, l0, h1, l1;
    size_t base = (size_t)m * (2 * DIM);

    split_bf16(tanhf(v.x), h0, l0);
    split_bf16(tanhf(v.y), h1, l1);
    __nv_bfloat162 ph; ph.x = h0; ph.y = h1;
    __nv_bfloat162 pl; pl.x = l0; pl.y = l1;
    *reinterpret_cast<__nv_bfloat162*>(g_gh + base + 2 * t) = ph;
    *reinterpret_cast<__nv_bfloat162*>(g_gl + base + 2 * t) = pl;

    split_bf16(tanhf(w.x), h0, l0);
    split_bf16(tanhf(w.y), h1, l1);
    ph.x = h0; ph.y = h1;
    pl.x = l0; pl.y = l1;
    *reinterpret_cast<__nv_bfloat162*>(g_gh + base + DIM + 2 * t) = ph;
    *reinterpret_cast<__nv_bfloat162*>(g_gl + base + DIM + 2 * t) = pl;
}

// ---------------------------------------------------------------------------
// GEMM2: rows = leaky_relu(g @ lin_w^T + lin_b) + bias, scattered into both
//        halves of d_out.  grid (4 n-tiles, 256 m-tiles), block 256, 2 CTAs/SM
// ---------------------------------------------------------------------------
__global__ __launch_bounds__(256, 2) void gemm2_kernel(
    const int* __restrict__ idxp, const int* __restrict__ idxk,
    const float* __restrict__ lin_b, const float* __restrict__ bias,
    float* __restrict__ out) {
    extern __shared__ __align__(16) __nv_bfloat16 sm[];
    const int tid = threadIdx.x, lane = tid & 31, wid = tid >> 5;
    const int wm = wid & 3, wn = wid >> 2;
    const int n0 = blockIdx.x * 128, m0 = blockIdx.y * 128;

    float* outp = out;
    float* outk = out + (size_t)NNODE * DIM;

    float acc[2][8][4];
#pragma unroll
    for (int i = 0; i < 2; ++i)
#pragma unroll
        for (int j = 0; j < 8; ++j)
#pragma unroll
            for (int k = 0; k < 4; ++k) acc[i][j][k] = 0.f;

    const uint32_t sb = smem_u32(sm);

    stage_cp(sb, g_gh, g_gl, g_lin_hi, g_lin_lo, 2 * DIM, 2 * DIM, m0, n0, 0, tid);
    cp_commit();

    const int S = (2 * DIM) / 32;   // 32 stages
#pragma unroll 1
    for (int s = 0; s < S; ++s) {
        if (s + 1 < S) {
            stage_cp(sb + ((s + 1) & 1) * BUF_BYTES, g_gh, g_gl, g_lin_hi, g_lin_lo,
                     2 * DIM, 2 * DIM, m0, n0, (s + 1) * 32, tid);
            cp_commit();
            cp_wait<1>();
        } else {
            cp_wait<0>();
        }
        __syncthreads();
        compute_stage(sb + (s & 1) * BUF_BYTES, lane, wm, wn, acc);
        __syncthreads();
    }

#pragma unroll
    for (int mt = 0; mt < 2; ++mt) {
        int grow = m0 + wm * 32 + mt * 16 + (lane >> 2);
        int p0 = idxp[grow], p1 = idxp[grow + 8];
        int q0 = idxk[grow], q1 = idxk[grow + 8];
#pragma unroll
        for (int nt = 0; nt < 8; ++nt) {
            int gcol = n0 + wn * 64 + nt * 8 + (lane & 3) * 2;
            float2 lb = *reinterpret_cast<const float2*>(lin_b + gcol);
            float2 bs = *reinterpret_cast<const float2*>(bias + gcol);
            float x0 = acc[mt][nt][0] + lb.x;
            float x1 = acc[mt][nt][1] + lb.y;
            float x2 = acc[mt][nt][2] + lb.x;
            float x3 = acc[mt][nt][3] + lb.y;
            x0 = (x0 >= 0.f ? x0 : 0.01f * x0) + bs.x;
            x1 = (x1 >= 0.f ? x1 : 0.01f * x1) + bs.y;
            x2 = (x2 >= 0.f ? x2 : 0.01f * x2) + bs.x;
            x3 = (x3 >= 0.f ? x3 : 0.01f * x3) + bs.y;
            float2 v0; v0.x = x0; v0.y = x1;
            float2 v1; v1.x = x2; v1.y = x3;
            *reinterpret_cast<float2*>(outp + (size_t)p0 * DIM + gcol) = v0;
            *reinterpret_cast<float2*>(outp + (size_t)p1 * DIM + gcol) = v1;
            *reinterpret_cast<float2*>(outk + (size_t)q0 * DIM + gcol) = v0;
            *reinterpret_cast<float2*>(outk + (size_t)q1 * DIM + gcol) = v1;
        }
    }
}

// ---------------------------------------------------------------------------
// Launch
// ---------------------------------------------------------------------------
extern "C" void kernel_launch(void* const* d_in, const int* in_sizes, int n_in,
                              void* d_out, int out_size) {
    const float* h_p  = (const float*)d_in[0];
    const float* h_k  = (const float*)d_in[1];
    const int*   idxp = (const int*)d_in[2];
    const int*   idxk = (const int*)d_in[3];
    // d_in[4] = last_x (unused by the reference computation)
    const float* wo   = (const float*)d_in[5];
    const float* wc   = (const float*)d_in[6];
    const float* lw   = (const float*)d_in[7];
    const float* lb   = (const float*)d_in[8];
    const float* bias = (const float*)d_in[9];
    float* out = (float*)d_out;

    cudaFuncSetAttribute(gemm1_kernel, cudaFuncAttributeMaxDynamicSharedMemorySize, SMEM_BYTES);
    cudaFuncSetAttribute(gemm2_kernel, cudaFuncAttributeMaxDynamicSharedMemorySize, SMEM_BYTES);

    prep_kernel<<<(512 * 1024) / 256, 256>>>(wo, wc, lw);

    split_inputs_kernel<<<dim3((NNODE * DIM / 2) / 256, 2), 256>>>(h_p, h_k);

    gemm1_kernel<<<dim3(DIM / 128, NNODE / 128, 2), 256, SMEM_BYTES>>>(out);

    gather_tanh_kernel<<<MMUT, 256>>>(out, idxp, idxk);

    gemm2_kernel<<<dim3(DIM / 128, MMUT / 128), 256, SMEM_BYTES>>>(idxp, idxk, lb, bias, out);
}

// round 9
// speedup vs baseline: 1.1212x; 1.0279x over previous
#include <cuda_runtime.h>
#include <cuda_bf16.h>
#include <cstdint>

// ---------------------------------------------------------------------------
// Problem constants
// ---------------------------------------------------------------------------
#define DIM   512
#define NNODE 65536
#define MMUT  32768

// ---------------------------------------------------------------------------
// Smem tile geometry: CTA tile 128x128, K-stage 32, rows padded to 40 bf16
// ---------------------------------------------------------------------------
#define RS      40                    // row stride in bf16 (80 bytes)
#define MAT_ELE (128 * RS)            // one 128x32(+pad) matrix = 5120 bf16
#define BUF_ELE (4 * MAT_ELE)         // A_hi, A_lo, B_hi, B_lo
#define BUF_BYTES (BUF_ELE * 2)       // 40960
#define SMEM_BYTES (2 * BUF_BYTES)    // double buffered = 81920 B

#define DI __device__ __forceinline__

// ---------------------------------------------------------------------------
// Device scratch (__device__ globals only — no allocations)
// ---------------------------------------------------------------------------
__device__ __nv_bfloat16 g_wo_hi[DIM * DIM];
__device__ __nv_bfloat16 g_wo_lo[DIM * DIM];
__device__ __nv_bfloat16 g_wc_hi[DIM * DIM];
__device__ __nv_bfloat16 g_wc_lo[DIM * DIM];
__device__ __nv_bfloat16 g_lin_hi[DIM * 2 * DIM];
__device__ __nv_bfloat16 g_lin_lo[DIM * 2 * DIM];
// pre-split inputs: h_p, h_k as bf16 hi/lo
__device__ __nv_bfloat16 g_hp_hi[(size_t)NNODE * DIM];
__device__ __nv_bfloat16 g_hp_lo[(size_t)NNODE * DIM];
__device__ __nv_bfloat16 g_hk_hi[(size_t)NNODE * DIM];
__device__ __nv_bfloat16 g_hk_lo[(size_t)NNODE * DIM];
// gathered + tanh'd + split GEMM2 A matrix: [MMUT, 1024] bf16 hi/lo
__device__ __nv_bfloat16 g_gh[(size_t)MMUT * 2 * DIM];
__device__ __nv_bfloat16 g_gl[(size_t)MMUT * 2 * DIM];

// ---------------------------------------------------------------------------
// Helpers
// ---------------------------------------------------------------------------
DI uint32_t smem_u32(const void* p) {
    uint32_t a;
    asm("{ .reg .u64 t; cvta.to.shared.u64 t, %1; cvt.u32.u64 %0, t; }"
        : "=r"(a) : "l"(p));
    return a;
}

DI void split_bf16(float v, __nv_bfloat16& h, __nv_bfloat16& l) {
    h = __float2bfloat16(v);
    l = __float2bfloat16(v - __bfloat162float(h));
}

DI void ldsm_x4(uint32_t* r, uint32_t addr) {
    asm volatile("ldmatrix.sync.aligned.m8n8.x4.shared.b16 {%0,%1,%2,%3}, [%4];"
                 : "=r"(r[0]), "=r"(r[1]), "=r"(r[2]), "=r"(r[3]) : "r"(addr));
}

DI void mma_bf16(float* c, const uint32_t* a, uint32_t b0, uint32_t b1) {
    asm volatile(
        "mma.sync.aligned.m16n8k16.row.col.f32.bf16.bf16.f32 "
        "{%0,%1,%2,%3}, {%4,%5,%6,%7}, {%8,%9}, {%0,%1,%2,%3};"
        : "+f"(c[0]), "+f"(c[1]), "+f"(c[2]), "+f"(c[3])
        : "r"(a[0]), "r"(a[1]), "r"(a[2]), "r"(a[3]), "r"(b0), "r"(b1));
}

DI void cp_async16(uint32_t saddr, const void* gptr) {
    asm volatile("cp.async.cg.shared.global [%0], [%1], 16;"
                 :: "r"(saddr), "l"(gptr));
}
DI void cp_commit() { asm volatile("cp.async.commit_group;" ::: "memory"); }
template <int N> DI void cp_wait() {
    asm volatile("cp.async.wait_group %0;" :: "n"(N) : "memory");
}

// ---------------------------------------------------------------------------
// One K-stage (32) of the split-bf16 warp-tile MMA: 2 k16 steps, warp 32x64.
// Product-major issue order: per B-fragment, 4 independent HMMAs per product
// class (hi*hi, lo*hi, hi*lo) so same-accumulator reuse distance is >=4.
// ---------------------------------------------------------------------------
DI void compute_stage(uint32_t base, int lane, int wm, int wn,
                      float acc[2][8][4]) {
    const uint32_t sAhi = base;
    const uint32_t sAlo = base + MAT_ELE * 2;
    const uint32_t sBhi = base + MAT_ELE * 4;
    const uint32_t sBlo = base + MAT_ELE * 6;
    const int lrow = lane & 15;
    const int lkh  = lane >> 4;
#pragma unroll
    for (int ks = 0; ks < 2; ++ks) {
        const uint32_t kbyte = (uint32_t)(ks * 16 + 8 * lkh) * 2;
        uint32_t ah[2][4], al[2][4];
#pragma unroll
        for (int mt = 0; mt < 2; ++mt) {
            uint32_t off = (uint32_t)((wm * 32 + mt * 16 + lrow) * (RS * 2)) + kbyte;
            ldsm_x4(ah[mt], sAhi + off);
            ldsm_x4(al[mt], sAlo + off);
        }
#pragma unroll
        for (int np = 0; np < 4; ++np) {
            uint32_t off = (uint32_t)((wn * 64 + np * 16 + lrow) * (RS * 2)) + kbyte;
            uint32_t bh[4], bl[4];
            ldsm_x4(bh, sBhi + off);
            ldsm_x4(bl, sBlo + off);
            // product-major: all hi*hi, then all lo*hi, then all hi*lo
#pragma unroll
            for (int mt = 0; mt < 2; ++mt)
#pragma unroll
                for (int w = 0; w < 2; ++w)
                    mma_bf16(acc[mt][np * 2 + w], ah[mt], bh[w], bh[w + 2]);
#pragma unroll
            for (int mt = 0; mt < 2; ++mt)
#pragma unroll
                for (int w = 0; w < 2; ++w)
                    mma_bf16(acc[mt][np * 2 + w], al[mt], bh[w], bh[w + 2]);
#pragma unroll
            for (int mt = 0; mt < 2; ++mt)
#pragma unroll
                for (int w = 0; w < 2; ++w)
                    mma_bf16(acc[mt][np * 2 + w], ah[mt], bl[w], bl[w + 2]);
        }
    }
}

// ---------------------------------------------------------------------------
// cp.async one stage: 4 matrices x 128 rows x 64B, 8 chunks of 16B per thread
// ---------------------------------------------------------------------------
DI void stage_cp(uint32_t sbase,
                 const __nv_bfloat16* Ah, const __nv_bfloat16* Al,
                 const __nv_bfloat16* Bh, const __nv_bfloat16* Bl,
                 int ldA, int ldB, int m0, int n0, int k0, int tid) {
    const int q = tid & 3;
    const int r = tid >> 2;
#pragma unroll
    for (int i = 0; i < 8; ++i) {
        const int mat = i >> 1;
        const int row = (i & 1) * 64 + r;
        const __nv_bfloat16* p = (mat == 0) ? Ah : (mat == 1) ? Al
                               : (mat == 2) ? Bh : Bl;
        const int ld = (mat < 2) ? ldA : ldB;
        const int r0 = (mat < 2) ? m0 : n0;
        uint32_t sa = sbase + (uint32_t)(mat * (MAT_ELE * 2) + row * (RS * 2) + q * 16);
        cp_async16(sa, p + (size_t)(r0 + row) * ld + k0 + q * 8);
    }
}

// ---------------------------------------------------------------------------
// prep: split weights to bf16 hi/lo (+ transpose W_o, W_c to [n][k])
// ---------------------------------------------------------------------------
__global__ void prep_kernel(const float* __restrict__ wo, const float* __restrict__ wc,
                            const float* __restrict__ lw) {
    int i = blockIdx.x * 256 + threadIdx.x;   // 0 .. 512*1024-1
    int n = i >> 10;
    int k = i & 1023;

    __nv_bfloat16 h, l;
    split_bf16(lw[i], h, l);                  // lin_w is [512][1024] = [n][k]
    g_lin_hi[i] = h;
    g_lin_lo[i] = l;

    if (k < 512) {
        int src = k * 512 + n;                // B[n][k] = W[k][n]
        int dst = n * 512 + k;
        split_bf16(wo[src], h, l);
        g_wo_hi[dst] = h; g_wo_lo[dst] = l;
        split_bf16(wc[src], h, l);
        g_wc_hi[dst] = h; g_wc_lo[dst] = l;
    }
}

// ---------------------------------------------------------------------------
// split inputs: h_p, h_k fp32 -> bf16 hi/lo  (pure bandwidth pass)
// ---------------------------------------------------------------------------
__global__ void split_inputs_kernel(const float* __restrict__ hp,
                                    const float* __restrict__ hk) {
    const size_t idx = (size_t)blockIdx.x * 256 + threadIdx.x;   // float4 index
    const int z = blockIdx.y;
    const float* src = z ? hk : hp;
    __nv_bfloat16* dh = z ? g_hk_hi : g_hp_hi;
    __nv_bfloat16* dl = z ? g_hk_lo : g_hp_lo;

    float4 v = *reinterpret_cast<const float4*>(src + idx * 4);
    __nv_bfloat16 h0, l0, h1, l1, h2, l2, h3, l3;
    split_bf16(v.x, h0, l0);
    split_bf16(v.y, h1, l1);
    split_bf16(v.z, h2, l2);
    split_bf16(v.w, h3, l3);
    __nv_bfloat162 ph0; ph0.x = h0; ph0.y = h1;
    __nv_bfloat162 ph1; ph1.x = h2; ph1.y = h3;
    __nv_bfloat162 pl0; pl0.x = l0; pl0.y = l1;
    __nv_bfloat162 pl1; pl1.x = l2; pl1.y = l3;
    uint2 uh; uh.x = *reinterpret_cast<uint32_t*>(&ph0); uh.y = *reinterpret_cast<uint32_t*>(&ph1);
    uint2 ul; ul.x = *reinterpret_cast<uint32_t*>(&pl0); ul.y = *reinterpret_cast<uint32_t*>(&pl1);
    *reinterpret_cast<uint2*>(dh + idx * 4) = uh;
    *reinterpret_cast<uint2*>(dl + idx * 4) = ul;
}

// ---------------------------------------------------------------------------
// GEMM1: trans_hp = h_p @ W_o ; trans_hk = h_k @ W_c   (all operands pre-split)
// grid (4 n-tiles, 512 m-tiles, 2), block 256, 2 CTAs/SM
// ---------------------------------------------------------------------------
__global__ __launch_bounds__(256, 2) void gemm1_kernel(float* __restrict__ out) {
    extern __shared__ __align__(16) __nv_bfloat16 sm[];
    const int tid = threadIdx.x, lane = tid & 31, wid = tid >> 5;
    const int wm = wid & 3, wn = wid >> 2;
    const int n0 = blockIdx.x * 128, m0 = blockIdx.y * 128, z = blockIdx.z;

    const __nv_bfloat16* Ah = z ? g_hk_hi : g_hp_hi;
    const __nv_bfloat16* Al = z ? g_hk_lo : g_hp_lo;
    const __nv_bfloat16* Bh = z ? g_wc_hi : g_wo_hi;
    const __nv_bfloat16* Bl = z ? g_wc_lo : g_wo_lo;
    float* dst = out + (size_t)z * NNODE * DIM;

    float acc[2][8][4];
#pragma unroll
    for (int i = 0; i < 2; ++i)
#pragma unroll
        for (int j = 0; j < 8; ++j)
#pragma unroll
            for (int k = 0; k < 4; ++k) acc[i][j][k] = 0.f;

    const uint32_t sb = smem_u32(sm);

    stage_cp(sb, Ah, Al, Bh, Bl, DIM, DIM, m0, n0, 0, tid);
    cp_commit();

    const int S = DIM / 32;   // 16 stages
#pragma unroll 1
    for (int s = 0; s < S; ++s) {
        if (s + 1 < S) {
            stage_cp(sb + ((s + 1) & 1) * BUF_BYTES, Ah, Al, Bh, Bl,
                     DIM, DIM, m0, n0, (s + 1) * 32, tid);
            cp_commit();
            cp_wait<1>();
        } else {
            cp_wait<0>();
        }
        __syncthreads();
        compute_stage(sb + (s & 1) * BUF_BYTES, lane, wm, wn, acc);
        __syncthreads();
    }

#pragma unroll
    for (int mt = 0; mt < 2; ++mt) {
        int grow = m0 + wm * 32 + mt * 16 + (lane >> 2);
#pragma unroll
        for (int nt = 0; nt < 8; ++nt) {
            int gcol = n0 + wn * 64 + nt * 8 + (lane & 3) * 2;
            float2 v0; v0.x = acc[mt][nt][0]; v0.y = acc[mt][nt][1];
            float2 v1; v1.x = acc[mt][nt][2]; v1.y = acc[mt][nt][3];
            *reinterpret_cast<float2*>(dst + (size_t)grow * DIM + gcol) = v0;
            *reinterpret_cast<float2*>(dst + (size_t)(grow + 8) * DIM + gcol) = v1;
        }
    }
}

// ---------------------------------------------------------------------------
// gather + tanh + bf16 split
// ---------------------------------------------------------------------------
__global__ void gather_tanh_kernel(const float* __restrict__ out,
                                   const int* __restrict__ idxp,
                                   const int* __restrict__ idxk) {
    const int m = blockIdx.x;
    const int t = threadIdx.x;                 // 256 threads, 2 cols each half
    const float* outp = out;
    const float* outk = out + (size_t)NNODE * DIM;
    const int rp = idxp[m], rk = idxk[m];

    float2 v = *reinterpret_cast<const float2*>(outp + (size_t)rp * DIM + 2 * t);
    float2 w = *reinterpret_cast<const float2*>(outk + (size_t)rk * DIM + 2 * t);

    __nv_bfloat16 h0, l0, h1, l1;
    size_t base = (size_t)m * (2 * DIM);

    split_bf16(tanhf(v.x), h0, l0);
    split_bf16(tanhf(v.y), h1, l1);
    __nv_bfloat162 ph; ph.x = h0; ph.y = h1;
    __nv_bfloat162 pl; pl.x = l0; pl.y = l1;
    *reinterpret_cast<__nv_bfloat162*>(g_gh + base + 2 * t) = ph;
    *reinterpret_cast<__nv_bfloat162*>(g_gl + base + 2 * t) = pl;

    split_bf16(tanhf(w.x), h0, l0);
    split_bf16(tanhf(w.y), h1, l1);
    ph.x = h0; ph.y = h1;
    pl.x = l0; pl.y = l1;
    *reinterpret_cast<__nv_bfloat162*>(g_gh + base + DIM + 2 * t) = ph;
    *reinterpret_cast<__nv_bfloat162*>(g_gl + base + DIM + 2 * t) = pl;
}

// ---------------------------------------------------------------------------
// GEMM2: rows = leaky_relu(g @ lin_w^T + lin_b) + bias, scattered into both
//        halves of d_out.  grid (4 n-tiles, 256 m-tiles), block 256, 2 CTAs/SM
// ---------------------------------------------------------------------------
__global__ __launch_bounds__(256, 2) void gemm2_kernel(
    const int* __restrict__ idxp, const int* __restrict__ idxk,
    const float* __restrict__ lin_b, const float* __restrict__ bias,
    float* __restrict__ out) {
    extern __shared__ __align__(16) __nv_bfloat16 sm[];
    const int tid = threadIdx.x, lane = tid & 31, wid = tid >> 5;
    const int wm = wid & 3, wn = wid >> 2;
    const int n0 = blockIdx.x * 128, m0 = blockIdx.y * 128;

    float* outp = out;
    float* outk = out + (size_t)NNODE * DIM;

    float acc[2][8][4];
#pragma unroll
    for (int i = 0; i < 2; ++i)
#pragma unroll
        for (int j = 0; j < 8; ++j)
#pragma unroll
            for (int k = 0; k < 4; ++k) acc[i][j][k] = 0.f;

    const uint32_t sb = smem_u32(sm);

    stage_cp(sb, g_gh, g_gl, g_lin_hi, g_lin_lo, 2 * DIM, 2 * DIM, m0, n0, 0, tid);
    cp_commit();

    const int S = (2 * DIM) / 32;   // 32 stages
#pragma unroll 1
    for (int s = 0; s < S; ++s) {
        if (s + 1 < S) {
            stage_cp(sb + ((s + 1) & 1) * BUF_BYTES, g_gh, g_gl, g_lin_hi, g_lin_lo,
                     2 * DIM, 2 * DIM, m0, n0, (s + 1) * 32, tid);
            cp_commit();
            cp_wait<1>();
        } else {
            cp_wait<0>();
        }
        __syncthreads();
        compute_stage(sb + (s & 1) * BUF_BYTES, lane, wm, wn, acc);
        __syncthreads();
    }

#pragma unroll
    for (int mt = 0; mt < 2; ++mt) {
        int grow = m0 + wm * 32 + mt * 16 + (lane >> 2);
        int p0 = idxp[grow], p1 = idxp[grow + 8];
        int q0 = idxk[grow], q1 = idxk[grow + 8];
#pragma unroll
        for (int nt = 0; nt < 8; ++nt) {
            int gcol = n0 + wn * 64 + nt * 8 + (lane & 3) * 2;
            float2 lb = *reinterpret_cast<const float2*>(lin_b + gcol);
            float2 bs = *reinterpret_cast<const float2*>(bias + gcol);
            float x0 = acc[mt][nt][0] + lb.x;
            float x1 = acc[mt][nt][1] + lb.y;
            float x2 = acc[mt][nt][2] + lb.x;
            float x3 = acc[mt][nt][3] + lb.y;
            x0 = (x0 >= 0.f ? x0 : 0.01f * x0) + bs.x;
            x1 = (x1 >= 0.f ? x1 : 0.01f * x1) + bs.y;
            x2 = (x2 >= 0.f ? x2 : 0.01f * x2) + bs.x;
            x3 = (x3 >= 0.f ? x3 : 0.01f * x3) + bs.y;
            float2 v0; v0.x = x0; v0.y = x1;
            float2 v1; v1.x = x2; v1.y = x3;
            *reinterpret_cast<float2*>(outp + (size_t)p0 * DIM + gcol) = v0;
            *reinterpret_cast<float2*>(outp + (size_t)p1 * DIM + gcol) = v1;
            *reinterpret_cast<float2*>(outk + (size_t)q0 * DIM + gcol) = v0;
            *reinterpret_cast<float2*>(outk + (size_t)q1 * DIM + gcol) = v1;
        }
    }
}

// ---------------------------------------------------------------------------
// Launch
// ---------------------------------------------------------------------------
extern "C" void kernel_launch(void* const* d_in, const int* in_sizes, int n_in,
                              void* d_out, int out_size) {
    const float* h_p  = (const float*)d_in[0];
    const float* h_k  = (const float*)d_in[1];
    const int*   idxp = (const int*)d_in[2];
    const int*   idxk = (const int*)d_in[3];
    // d_in[4] = last_x (unused by the reference computation)
    const float* wo   = (const float*)d_in[5];
    const float* wc   = (const float*)d_in[6];
    const float* lw   = (const float*)d_in[7];
    const float* lb   = (const float*)d_in[8];
    const float* bias = (const float*)d_in[9];
    float* out = (float*)d_out;

    cudaFuncSetAttribute(gemm1_kernel, cudaFuncAttributeMaxDynamicSharedMemorySize, SMEM_BYTES);
    cudaFuncSetAttribute(gemm2_kernel, cudaFuncAttributeMaxDynamicSharedMemorySize, SMEM_BYTES);

    prep_kernel<<<(512 * 1024) / 256, 256>>>(wo, wc, lw);

    split_inputs_kernel<<<dim3((NNODE * DIM / 4) / 256, 2), 256>>>(h_p, h_k);

    gemm1_kernel<<<dim3(DIM / 128, NNODE / 128, 2), 256, SMEM_BYTES>>>(out);

    gather_tanh_kernel<<<MMUT, 256>>>(out, idxp, idxk);

    gemm2_kernel<<<dim3(DIM / 128, MMUT / 128), 256, SMEM_BYTES>>>(idxp, idxk, lb, bias, out);
}